// round 16
// baseline (speedup 1.0000x reference)
#include <cuda_runtime.h>
#include <cuda_bf16.h>
#include <cuda_fp16.h>
#include <cstdint>

#define BDIM 2
#define CH   512
#define CQ   64
#define NN   4096
#define NSPLIT 8

typedef __nv_bfloat16 bf16;

// ---------------------------------------------------------------------------
// Scratch. g_energy is fp16; softmax overwrites it in place with bf16 att.
// ---------------------------------------------------------------------------
__device__ __align__(256) __half g_energy[(size_t)BDIM * NN * NN];   // 67 MB
__device__ __align__(256) float g_xb    [(size_t)BDIM * CH * NN];    // tf32 c-major (gram)
__device__ __align__(256) bf16  g_xbt_b [(size_t)BDIM * NN * CH];    // bf16 n-major
__device__ __align__(256) bf16  g_vb    [(size_t)BDIM * CH * NN];
__device__ __align__(256) bf16  g_qkt   [(size_t)BDIM * NN * 128];   // bf16 [n][q|k]
__device__ __align__(256) float g_pos   [(size_t)BDIM * CH * NN];
__device__ __align__(256) float g_gramp [(size_t)BDIM * NSPLIT * CH * CH];
__device__ __align__(256) bf16  g_attcb [(size_t)BDIM * CH * CH];
__device__ __align__(256) bf16  g_wqk [128 * CH];
__device__ __align__(256) float g_bqk [128];
__device__ __align__(256) bf16  g_wvr [CH * CH];

// ---------------------------------------------------------------------------
__device__ __forceinline__ uint32_t smem_u32(const void* p) {
    uint32_t a;
    asm("{ .reg .u64 t; cvta.to.shared.u64 t, %1; cvt.u32.u64 %0, t; }"
        : "=r"(a) : "l"(p));
    return a;
}
__device__ __forceinline__ float tf32r(float x) {
    uint32_t u;
    asm("cvt.rna.tf32.f32 %0, %1;" : "=r"(u) : "f"(x));
    return __uint_as_float(u);
}

#define CP_ASYNC16(dst, src, sz) \
    asm volatile("cp.async.cg.shared.global [%0], [%1], 16, %2;" \
                 :: "r"(dst), "l"(src), "r"(sz))
#define CP_COMMIT() asm volatile("cp.async.commit_group;")
#define CP_WAIT(N)  asm volatile("cp.async.wait_group %0;" :: "n"(N))

#define MMA1688(d, a, b) \
    asm volatile("mma.sync.aligned.m16n8k8.row.col.f32.tf32.tf32.f32 " \
                 "{%0,%1,%2,%3}, {%4,%5,%6,%7}, {%8,%9}, {%0,%1,%2,%3};" \
                 : "+f"((d)[0]), "+f"((d)[1]), "+f"((d)[2]), "+f"((d)[3]) \
                 : "r"((a)[0]), "r"((a)[1]), "r"((a)[2]), "r"((a)[3]), \
                   "r"((b)[0]), "r"((b)[1]))

#define MMA16816(d, a, b) \
    asm volatile("mma.sync.aligned.m16n8k16.row.col.f32.bf16.bf16.f32 " \
                 "{%0,%1,%2,%3}, {%4,%5,%6,%7}, {%8,%9}, {%0,%1,%2,%3};" \
                 : "+f"((d)[0]), "+f"((d)[1]), "+f"((d)[2]), "+f"((d)[3]) \
                 : "r"((a)[0]), "r"((a)[1]), "r"((a)[2]), "r"((a)[3]), \
                   "r"((b)[0]), "r"((b)[1]))

#define LDSM4(R, addr) \
    asm volatile("ldmatrix.sync.aligned.m8n8.x4.shared.b16 {%0,%1,%2,%3}, [%4];" \
                 : "=r"((R)[0]), "=r"((R)[1]), "=r"((R)[2]), "=r"((R)[3]) \
                 : "r"(addr))

// ---------------------------------------------------------------------------
// tf32 GEMM (gram only). BM128 x BN256 x BK32, 256 thr, 3-stage pipeline.
// ---------------------------------------------------------------------------
__global__ __launch_bounds__(256)
void tf_gemm(const float* __restrict__ A, const float* __restrict__ B,
             float* __restrict__ Cout,
             int Mrows, int Nrows, int K, int lda, int ldb, int nsplit,
             long long sA, long long sB, long long sC)
{
    extern __shared__ __align__(128) uint8_t smem[];

    const int tid  = threadIdx.x;
    const int lane = tid & 31;
    const int warp = tid >> 5;
    const int mw   = warp >> 2;
    const int nw   = warp & 3;
    const int z    = blockIdx.z;
    const int bat  = z / nsplit;
    const int sp   = z - bat * nsplit;
    const int m0   = blockIdx.y * 128;
    const int n0   = blockIdx.x * 256;

    A += (long long)bat * sA + (long long)sp * K;
    B += (long long)bat * sB + (long long)sp * K;

    const uint32_t sbase = smem_u32(smem);
    const int KI = K >> 5;

    auto load_tile = [&](int it) {
        const int k0 = it << 5;
        const uint32_t st = sbase + (uint32_t)(it % 3) * 49152;
#pragma unroll
        for (int i = 0; i < 12; ++i) {
            int idx = tid + i * 256;
            if (idx < 1024) {
                int r = idx >> 3, c = idx & 7;
                int grow = m0 + r;
                int ok = (grow < Mrows);
                const float* src = A + (long long)(ok ? grow : 0) * lda + k0 + c * 4;
                uint32_t dst = st + r * 128 + ((c ^ (r & 7)) << 4);
                CP_ASYNC16(dst, src, ok ? 16 : 0);
            } else {
                int bi = idx - 1024;
                int r = bi >> 3, c = bi & 7;
                int grow = n0 + r;
                int ok = (grow < Nrows);
                const float* src = B + (long long)(ok ? grow : 0) * ldb + k0 + c * 4;
                uint32_t dst = st + 16384 + r * 128 + ((c ^ (r & 7)) << 4);
                CP_ASYNC16(dst, src, ok ? 16 : 0);
            }
        }
    };

    float acc[4][8][4];
#pragma unroll
    for (int i = 0; i < 4; ++i)
#pragma unroll
        for (int j = 0; j < 8; ++j)
#pragma unroll
            for (int r = 0; r < 4; ++r) acc[i][j][r] = 0.f;

    load_tile(0); CP_COMMIT();
    if (KI > 1) { load_tile(1); CP_COMMIT(); }

    const int g  = lane >> 2;
    const int tq = lane & 3;

    for (int it = 0; it < KI; ++it) {
        if (it + 1 < KI) CP_WAIT(1); else CP_WAIT(0);
        __syncthreads();
        if (it + 2 < KI) { load_tile(it + 2); CP_COMMIT(); }

        const uint8_t* aP = smem + (it % 3) * 49152;
        const uint8_t* bP = aP + 16384;
        auto LDF = [&](const uint8_t* base, int r, int k) -> uint32_t {
            int off = r * 128 + (((k >> 2) ^ (r & 7)) << 4) + (k & 3) * 4;
            return *(const uint32_t*)(base + off);
        };

#pragma unroll
        for (int ks = 0; ks < 4; ++ks) {
            const int kb = ks * 8;
            uint32_t a[4][4];
#pragma unroll
            for (int mi = 0; mi < 4; ++mi) {
                int r0 = mw * 64 + mi * 16 + g;
                a[mi][0] = LDF(aP, r0,     kb + tq);
                a[mi][1] = LDF(aP, r0 + 8, kb + tq);
                a[mi][2] = LDF(aP, r0,     kb + tq + 4);
                a[mi][3] = LDF(aP, r0 + 8, kb + tq + 4);
            }
            uint32_t b[8][2];
#pragma unroll
            for (int ni = 0; ni < 8; ++ni) {
                int rn = nw * 64 + ni * 8 + g;
                b[ni][0] = LDF(bP, rn, kb + tq);
                b[ni][1] = LDF(bP, rn, kb + tq + 4);
            }
#pragma unroll
            for (int mi = 0; mi < 4; ++mi)
#pragma unroll
                for (int ni = 0; ni < 8; ++ni)
                    MMA1688(acc[mi][ni], a[mi], b[ni]);
        }
    }

    float* C = Cout + (long long)z * sC;
#pragma unroll
    for (int mi = 0; mi < 4; ++mi) {
#pragma unroll
        for (int half = 0; half < 2; ++half) {
            int m = m0 + mw * 64 + mi * 16 + g + half * 8;
            if (m >= Mrows) continue;
#pragma unroll
            for (int ni = 0; ni < 8; ++ni) {
                int n = n0 + nw * 64 + ni * 8 + tq * 2;
                if (n + 1 < Nrows)
                    *(float2*)&C[(long long)m * Nrows + n] =
                        make_float2(acc[mi][ni][half * 2], acc[mi][ni][half * 2 + 1]);
                else if (n < Nrows)
                    C[(long long)m * Nrows + n] = acc[mi][ni][half * 2];
            }
        }
    }
}

// ---------------------------------------------------------------------------
// bf16 GEMM, BM128 x BN256 x BK64, 512 threads (16 warps, 4x4, 32x64 warp
// tile), ldmatrix + m16n8k16, 3-stage pipeline (48 KB/stage).
// OM: 0=f32 row-major, 3=combine epilogue, 4=bf16 row-major,
//     5=bf16 transposed (C[n*M+m]), 6=fp16 row-major
// ---------------------------------------------------------------------------
template <int OM, bool HAS_BIAS>
__global__ __launch_bounds__(512)
void bf_gemm(const bf16* __restrict__ A, const bf16* __restrict__ B,
             void* __restrict__ Cout, const float* __restrict__ bias,
             int Mrows, int Nrows, int K, int lda, int ldb,
             long long sA, long long sB, long long sC,
             const float* __restrict__ P, const float* __restrict__ X,
             long long sPX,
             const float* __restrict__ s_alpha, const float* __restrict__ s_beta,
             const float* __restrict__ s_gp, const float* __restrict__ s_gc)
{
    extern __shared__ __align__(128) uint8_t smem[];   // 3 * 48 KB

    const int tid  = threadIdx.x;
    const int lane = tid & 31;
    const int warp = tid >> 5;
    const int mw   = warp >> 2;
    const int nw   = warp & 3;
    const int z    = blockIdx.z;
    const int m0   = blockIdx.y * 128;
    const int n0   = blockIdx.x * 256;

    A += (long long)z * sA;
    B += (long long)z * sB;

    const uint32_t sbase = smem_u32(smem);
    const int KI = K >> 6;

    auto load_tile = [&](int it) {
        const int k0 = it << 6;
        const uint32_t st = sbase + (uint32_t)(it % 3) * 49152;
#pragma unroll
        for (int i = 0; i < 6; ++i) {
            int idx = tid + i * 512;
            if (idx < 1024) {
                int r = idx >> 3, c = idx & 7;
                int grow = m0 + r;
                int ok = (grow < Mrows);
                const bf16* src = A + (long long)(ok ? grow : 0) * lda + k0 + c * 8;
                uint32_t dst = st + r * 128 + ((c ^ (r & 7)) << 4);
                CP_ASYNC16(dst, src, ok ? 16 : 0);
            } else {
                int bi = idx - 1024;
                int r = bi >> 3, c = bi & 7;
                int grow = n0 + r;
                int ok = (grow < Nrows);
                const bf16* src = B + (long long)(ok ? grow : 0) * ldb + k0 + c * 8;
                uint32_t dst = st + 16384 + r * 128 + ((c ^ (r & 7)) << 4);
                CP_ASYNC16(dst, src, ok ? 16 : 0);
            }
        }
    };

    float acc[2][8][4];
#pragma unroll
    for (int i = 0; i < 2; ++i)
#pragma unroll
        for (int j = 0; j < 8; ++j)
#pragma unroll
            for (int r = 0; r < 4; ++r) acc[i][j][r] = 0.f;

    load_tile(0); CP_COMMIT();
    if (KI > 1) { load_tile(1); CP_COMMIT(); }

    const int sub  = lane >> 3;
    const int lrow = lane & 7;

    for (int it = 0; it < KI; ++it) {
        if (it + 1 < KI) CP_WAIT(1); else CP_WAIT(0);
        __syncthreads();
        if (it + 2 < KI) { load_tile(it + 2); CP_COMMIT(); }

        const uint32_t aB = sbase + (uint32_t)(it % 3) * 49152;
        const uint32_t bB = aB + 16384;

#pragma unroll
        for (int ks = 0; ks < 4; ++ks) {
            uint32_t a[2][4];
#pragma unroll
            for (int mi = 0; mi < 2; ++mi) {
                int row = mw * 32 + mi * 16 + (sub & 1) * 8 + lrow;
                int kc  = ks * 2 + (sub >> 1);
                uint32_t addr = aB + row * 128 + ((kc ^ (row & 7)) << 4);
                LDSM4(a[mi], addr);
            }
            uint32_t b[8][2];
#pragma unroll
            for (int p = 0; p < 4; ++p) {
                int row = nw * 64 + p * 16 + (sub >> 1) * 8 + lrow;
                int kc  = ks * 2 + (sub & 1);
                uint32_t addr = bB + row * 128 + ((kc ^ (row & 7)) << 4);
                uint32_t t[4];
                LDSM4(t, addr);
                b[2 * p][0]     = t[0];
                b[2 * p][1]     = t[1];
                b[2 * p + 1][0] = t[2];
                b[2 * p + 1][1] = t[3];
            }
#pragma unroll
            for (int mi = 0; mi < 2; ++mi)
#pragma unroll
                for (int ni = 0; ni < 8; ++ni)
                    MMA16816(acc[mi][ni], a[mi], b[ni]);
        }
    }

    float c1 = 0.f, c2 = 1.f, c3 = 0.f;
    if (OM == 3) {
        float al = *s_alpha, be = *s_beta;
        c1 = al * (*s_gp);
        c2 = be * (*s_gc);
        c3 = al + be + 1.f;
        P += (long long)z * sPX;
        X += (long long)z * sPX;
    }
    float*  Cf = (float*)Cout + (long long)z * sC;
    bf16*   Cb = (bf16*)Cout + (long long)z * sC;
    __half* Ch = (__half*)Cout + (long long)z * sC;

    const int g  = lane >> 2;
    const int tq = lane & 3;

#pragma unroll
    for (int mi = 0; mi < 2; ++mi) {
#pragma unroll
        for (int half = 0; half < 2; ++half) {
            int m = m0 + mw * 32 + mi * 16 + g + half * 8;
            if (m >= Mrows) continue;
            float bv = HAS_BIAS ? bias[m] : 0.f;
#pragma unroll
            for (int ni = 0; ni < 8; ++ni) {
                int n = n0 + nw * 64 + ni * 8 + tq * 2;
                float v0 = acc[mi][ni][half * 2 + 0] + bv;
                float v1 = acc[mi][ni][half * 2 + 1] + bv;
                if (OM == 5) {
                    if (n < Nrows)     Cb[(long long)n * Mrows + m]       = __float2bfloat16(v0);
                    if (n + 1 < Nrows) Cb[(long long)(n + 1) * Mrows + m] = __float2bfloat16(v1);
                } else if (n + 1 < Nrows) {
                    long long idx = (long long)m * Nrows + n;
                    if (OM == 0) {
                        *(float2*)&Cf[idx] = make_float2(v0, v1);
                    } else if (OM == 3) {
                        Cf[idx]     = c1 * P[idx]     + c2 * v0 + c3 * X[idx];
                        Cf[idx + 1] = c1 * P[idx + 1] + c2 * v1 + c3 * X[idx + 1];
                    } else if (OM == 4) {
                        uint32_t pk = ((uint32_t)__bfloat16_as_ushort(__float2bfloat16(v1)) << 16)
                                    | (uint32_t)__bfloat16_as_ushort(__float2bfloat16(v0));
                        *(uint32_t*)&Cb[idx] = pk;
                    } else { // OM == 6
                        __half2 h = __floats2half2_rn(v0, v1);
                        *(__half2*)&Ch[idx] = h;
                    }
                } else if (n < Nrows) {
                    long long idx = (long long)m * Nrows + n;
                    if (OM == 0)      Cf[idx] = v0;
                    else if (OM == 3) Cf[idx] = c1 * P[idx] + c2 * v0 + c3 * X[idx];
                    else if (OM == 4) Cb[idx] = __float2bfloat16(v0);
                    else              Ch[idx] = __float2half_rn(v0);
                }
            }
        }
    }
}

// ---------------------------------------------------------------------------
__global__ __launch_bounds__(256)
void convert_x_k(const float* __restrict__ x, float* __restrict__ xb,
                 bf16* __restrict__ xbt_b)
{
    __shared__ float t[32][33];
    const int z = blockIdx.z;
    const float* xp = x + (size_t)z * CH * NN;
    float* xbp = xb + (size_t)z * CH * NN;
    bf16*  xtb = xbt_b + (size_t)z * NN * CH;
    const int n0 = blockIdx.x * 32, c0 = blockIdx.y * 32;
    const int tx = threadIdx.x, ty = threadIdx.y;
#pragma unroll
    for (int k = 0; k < 4; ++k) {
        int c = ty + k * 8;
        float raw = xp[(size_t)(c0 + c) * NN + n0 + tx];
        t[c][tx] = raw;
        xbp[(size_t)(c0 + c) * NN + n0 + tx] = tf32r(raw);
    }
    __syncthreads();
#pragma unroll
    for (int k = 0; k < 4; ++k) {
        int n = ty + k * 8;
        xtb[(size_t)(n0 + n) * CH + c0 + tx] = __float2bfloat16(t[tx][n]);
    }
}

__global__ __launch_bounds__(256)
void prep_weights_k(const float* __restrict__ wq, const float* __restrict__ wk,
                    const float* __restrict__ bq, const float* __restrict__ bk,
                    const float* __restrict__ wv,
                    bf16* __restrict__ wqk, float* __restrict__ bqk,
                    bf16* __restrict__ wvr)
{
    int i = blockIdx.x * 256 + threadIdx.x;
    if (i < 128 * CH) {
        int row = i >> 9;
        float v = (row < 64) ? wq[i] : wk[i - 64 * CH];
        wqk[i] = __float2bfloat16(v);
    }
    if (i < 128) bqk[i] = (i < 64) ? bq[i] : bk[i - 64];
    if (i < CH * CH) wvr[i] = __float2bfloat16(wv[i]);
}

// ---------------------------------------------------------------------------
// Row softmax (single batch, pointer pre-offset): fp16 in, bf16 out IN PLACE.
// Vectorized uint4 (8 halves) accesses: 512 uint4/row over 256 threads.
// ---------------------------------------------------------------------------
__global__ __launch_bounds__(256)
void softmax_pos(__half* __restrict__ energy)
{
    uint4* pv = (uint4*)(energy + (size_t)blockIdx.x * NN);
    const int tid = threadIdx.x;
    __shared__ float red[8];

    float v[16];
    uint4 w[2];
    float mx = -1e30f;
#pragma unroll
    for (int i = 0; i < 2; ++i) {
        w[i] = pv[tid + i * 256];
        const __half2* h2 = (const __half2*)&w[i];
#pragma unroll
        for (int j = 0; j < 4; ++j) {
            float2 f = __half22float2(h2[j]);
            v[i * 8 + j * 2]     = f.x;
            v[i * 8 + j * 2 + 1] = f.y;
        }
    }
#pragma unroll
    for (int i = 0; i < 16; ++i) mx = fmaxf(mx, v[i]);
#pragma unroll
    for (int o2 = 16; o2; o2 >>= 1) mx = fmaxf(mx, __shfl_xor_sync(~0u, mx, o2));
    if ((tid & 31) == 0) red[tid >> 5] = mx;
    __syncthreads();
    mx = red[0];
#pragma unroll
    for (int i = 1; i < 8; ++i) mx = fmaxf(mx, red[i]);

    float s = 0.f;
#pragma unroll
    for (int i = 0; i < 16; ++i) { v[i] = expf(v[i] - mx); s += v[i]; }
#pragma unroll
    for (int o2 = 16; o2; o2 >>= 1) s += __shfl_xor_sync(~0u, s, o2);
    __syncthreads();
    if ((tid & 31) == 0) red[tid >> 5] = s;
    __syncthreads();
    s = 0.f;
#pragma unroll
    for (int i = 0; i < 8; ++i) s += red[i];
    float inv = 1.f / s;

#pragma unroll
    for (int i = 0; i < 2; ++i) {
        uint4 o;
        __nv_bfloat162* b2 = (__nv_bfloat162*)&o;
#pragma unroll
        for (int j = 0; j < 4; ++j)
            b2[j] = __floats2bfloat162_rn(v[i * 8 + j * 2] * inv,
                                          v[i * 8 + j * 2 + 1] * inv);
        pv[tid + i * 256] = o;
    }
}

// ---------------------------------------------------------------------------
__global__ __launch_bounds__(128)
void softmax_chan(const float* __restrict__ gramp, bf16* __restrict__ attcb)
{
    const int bat = blockIdx.y;
    const int row = blockIdx.x;
    const float* base = gramp + ((size_t)bat * NSPLIT) * CH * CH + (size_t)row * CH;
    bf16* o = attcb + ((size_t)bat * CH + row) * CH;
    const int tid = threadIdx.x;
    __shared__ float red[4];

    float v[4];
    float mn = 1e30f;
#pragma unroll
    for (int i = 0; i < 4; ++i) {
        float s = 0.f;
#pragma unroll
        for (int sp = 0; sp < NSPLIT; ++sp)
            s += base[(size_t)sp * CH * CH + tid + i * 128];
        v[i] = s;
        mn = fminf(mn, s);
    }
#pragma unroll
    for (int o2 = 16; o2; o2 >>= 1) mn = fminf(mn, __shfl_xor_sync(~0u, mn, o2));
    if ((tid & 31) == 0) red[tid >> 5] = mn;
    __syncthreads();
    mn = fminf(fminf(red[0], red[1]), fminf(red[2], red[3]));

    float s = 0.f;
#pragma unroll
    for (int i = 0; i < 4; ++i) { v[i] = expf(mn - v[i]); s += v[i]; }
#pragma unroll
    for (int o2 = 16; o2; o2 >>= 1) s += __shfl_xor_sync(~0u, s, o2);
    __syncthreads();
    if ((tid & 31) == 0) red[tid >> 5] = s;
    __syncthreads();
    s = red[0] + red[1] + red[2] + red[3];
    float inv = 1.f / s;
#pragma unroll
    for (int i = 0; i < 4; ++i) o[tid + i * 128] = __float2bfloat16(v[i] * inv);
}

// ---------------------------------------------------------------------------
extern "C" void kernel_launch(void* const* d_in, const int* in_sizes, int n_in,
                              void* d_out, int out_size)
{
    const float* x  = (const float*)d_in[0];
    const float* wq = (const float*)d_in[1];
    const float* bq = (const float*)d_in[2];
    const float* wk = (const float*)d_in[3];
    const float* bk = (const float*)d_in[4];
    const float* wv = (const float*)d_in[5];
    const float* bv = (const float*)d_in[6];
    const float* gp = (const float*)d_in[7];
    const float* gc = (const float*)d_in[8];
    const float* al = (const float*)d_in[9];
    const float* be = (const float*)d_in[10];
    float* out = (float*)d_out;

    __half* energy;
    float *xb, *pos, *gramp, *bqk;
    bf16 *xbt_b, *vb, *qkt, *attcb, *wqk, *wvr;
    cudaGetSymbolAddress((void**)&energy, g_energy);
    cudaGetSymbolAddress((void**)&xb,    g_xb);
    cudaGetSymbolAddress((void**)&xbt_b, g_xbt_b);
    cudaGetSymbolAddress((void**)&vb,    g_vb);
    cudaGetSymbolAddress((void**)&qkt,   g_qkt);
    cudaGetSymbolAddress((void**)&pos,   g_pos);
    cudaGetSymbolAddress((void**)&gramp, g_gramp);
    cudaGetSymbolAddress((void**)&attcb, g_attcb);
    cudaGetSymbolAddress((void**)&wqk,   g_wqk);
    cudaGetSymbolAddress((void**)&bqk,   g_bqk);
    cudaGetSymbolAddress((void**)&wvr,   g_wvr);

    const long long sX   = (long long)CH * NN;
    const long long sXT  = (long long)NN * CH;
    const long long sQK  = (long long)NN * 128;
    const long long sAtt = (long long)NN * NN;
    const long long sGr  = (long long)CH * CH;

    const int SMEM_T = 3 * 49152;
    const int SMEM_B = 3 * 49152;

    static bool init_done = false;
    static cudaStream_t sA, sB;
    static cudaEvent_t evFork, evQK, evV, evS1, evA, evB;
    if (!init_done) {
        cudaFuncSetAttribute(tf_gemm, cudaFuncAttributeMaxDynamicSharedMemorySize, SMEM_T);
        cudaFuncSetAttribute(bf_gemm<5, true>,  cudaFuncAttributeMaxDynamicSharedMemorySize, SMEM_B);
        cudaFuncSetAttribute(bf_gemm<4, true>,  cudaFuncAttributeMaxDynamicSharedMemorySize, SMEM_B);
        cudaFuncSetAttribute(bf_gemm<6, false>, cudaFuncAttributeMaxDynamicSharedMemorySize, SMEM_B);
        cudaFuncSetAttribute(bf_gemm<0, false>, cudaFuncAttributeMaxDynamicSharedMemorySize, SMEM_B);
        cudaFuncSetAttribute(bf_gemm<3, false>, cudaFuncAttributeMaxDynamicSharedMemorySize, SMEM_B);
        cudaStreamCreateWithFlags(&sA, cudaStreamNonBlocking);
        cudaStreamCreateWithFlags(&sB, cudaStreamNonBlocking);
        cudaEventCreateWithFlags(&evFork, cudaEventDisableTiming);
        cudaEventCreateWithFlags(&evQK,   cudaEventDisableTiming);
        cudaEventCreateWithFlags(&evV,    cudaEventDisableTiming);
        cudaEventCreateWithFlags(&evS1,   cudaEventDisableTiming);
        cudaEventCreateWithFlags(&evA,    cudaEventDisableTiming);
        cudaEventCreateWithFlags(&evB,    cudaEventDisableTiming);
        init_done = true;
    }

    // ---- prologue on the default (capture) stream ----
    convert_x_k<<<dim3(NN / 32, CH / 32, BDIM), dim3(32, 8)>>>(x, xb, xbt_b);
    prep_weights_k<<<(CH * CH + 255) / 256, 256>>>(wq, wk, bq, bk, wv, wqk, bqk, wvr);

    // ---- fork ----
    cudaEventRecord(evFork, 0);
    cudaStreamWaitEvent(sA, evFork, 0);
    cudaStreamWaitEvent(sB, evFork, 0);

    // sA: qk-proj (both batches)
    bf_gemm<5, true><<<dim3(NN / 256, 1, BDIM), 512, SMEM_B, sA>>>(
        wqk, xbt_b, qkt, bqk, 128, NN, CH, CH, CH, 0, sXT, sQK,
        nullptr, nullptr, 0, nullptr, nullptr, nullptr, nullptr);
    cudaEventRecord(evQK, sA);

    // sB: v-proj (both batches)
    bf_gemm<4, true><<<dim3(NN / 256, CH / 128, BDIM), 512, SMEM_B, sB>>>(
        wvr, xbt_b, vb, bv, CH, NN, CH, CH, CH, 0, sXT, sX,
        nullptr, nullptr, 0, nullptr, nullptr, nullptr, nullptr);
    cudaEventRecord(evV, sB);

    // sA: energy(b0) -> softmax(b0)
    bf_gemm<6, false><<<dim3(NN / 256, NN / 128, 1), 512, SMEM_B, sA>>>(
        qkt, qkt + 64, energy, nullptr, NN, NN, CQ, 128, 128, 0, 0, 0,
        nullptr, nullptr, 0, nullptr, nullptr, nullptr, nullptr);
    softmax_pos<<<dim3(NN, 1), 256, 0, sA>>>(energy);

    // sB: gram -> chan softmax, then energy(b1) -> softmax(b1)
    tf_gemm<<<dim3(CH / 256, CH / 128, BDIM * NSPLIT), 256, SMEM_T, sB>>>(
        xb, xb, gramp, CH, CH, NN / NSPLIT, NN, NN, NSPLIT, sX, sX, sGr);
    softmax_chan<<<dim3(CH, BDIM), 128, 0, sB>>>(gramp, attcb);
    cudaStreamWaitEvent(sB, evQK, 0);
    bf_gemm<6, false><<<dim3(NN / 256, NN / 128, 1), 512, SMEM_B, sB>>>(
        qkt + sQK, qkt + sQK + 64, energy + sAtt, nullptr,
        NN, NN, CQ, 128, 128, 0, 0, 0,
        nullptr, nullptr, 0, nullptr, nullptr, nullptr, nullptr);
    softmax_pos<<<dim3(NN, 1), 256, 0, sB>>>(energy + sAtt);
    cudaEventRecord(evS1, sB);

    // sA: pos(b0) (needs vb), then pos(b1) (needs softmax b1)
    cudaStreamWaitEvent(sA, evV, 0);
    bf_gemm<0, false><<<dim3(NN / 256, CH / 128, 1), 512, SMEM_B, sA>>>(
        vb, (const bf16*)energy, pos, nullptr, CH, NN, NN, NN, NN, 0, 0, 0,
        nullptr, nullptr, 0, nullptr, nullptr, nullptr, nullptr);
    cudaStreamWaitEvent(sA, evS1, 0);
    bf_gemm<0, false><<<dim3(NN / 256, CH / 128, 1), 512, SMEM_B, sA>>>(
        vb + sX, (const bf16*)(energy + sAtt), pos + sX, nullptr,
        CH, NN, NN, NN, NN, 0, 0, 0,
        nullptr, nullptr, 0, nullptr, nullptr, nullptr, nullptr);

    // ---- join ----
    cudaEventRecord(evA, sA);
    cudaEventRecord(evB, sB);
    cudaStreamWaitEvent(0, evA, 0);
    cudaStreamWaitEvent(0, evB, 0);

    // combine (both batches) on default stream
    bf_gemm<3, false><<<dim3(NN / 256, CH / 128, BDIM), 512, SMEM_B>>>(
        attcb, xbt_b, out, nullptr, CH, NN, CH, CH, CH, sGr, sXT, sX,
        pos, x, sX, al, be, gp, gc);
}